// round 2
// baseline (speedup 1.0000x reference)
#include <cuda_runtime.h>

#define WS 16
#define NH 8
#define CH 96
#define DH 12          // CH / NH
#define NTOK 256       // WS*WS tokens per window
#define BATCH 8
#define IMG 256        // H = W
#define HW (IMG*IMG)   // 65536
#define NWIN 2048      // BATCH * 16 * 16
#define NPIX (BATCH*HW)        // 524288
#define TOTAL (BATCH*CH*HW)    // 50331648
#define EPS 1e-6f
#define BN_EPS 1e-5f
#define QSTR 257       // padded row stride for qkv smem

// scratch (device globals: allocation-free rule)
__device__ float g_out[TOTAL];   // attention output (pre-proj)
__device__ float g_y[TOTAL];     // proj output (pre-BN)
__device__ float g_sum[CH];
__device__ float g_sq[CH];
__device__ float g_scale[CH];
__device__ float g_shift[CH];

// ---------------------------------------------------------------------------
// K0: zero BN accumulators (graph-replay safe)
// ---------------------------------------------------------------------------
__global__ void k_zero() {
    int t = threadIdx.x;
    if (t < CH) { g_sum[t] = 0.f; g_sq[t] = 0.f; }
}

// ---------------------------------------------------------------------------
// K1: per-window qkv GEMM + linear attention.  One CTA = one 16x16 window.
// smem: x_s[96][256] | w_s[36][96] | qkv_s[36][257] | kv_s[144] | ksum[12] | vsum[12]
// ---------------------------------------------------------------------------
__global__ void __launch_bounds__(256, 1)
k_qkv_attn(const float* __restrict__ x, const float* __restrict__ w_qkv)
{
    extern __shared__ float smem[];
    float* x_s    = smem;                     // 24576 floats
    float* w_s    = x_s + CH*NTOK;            // 3456
    float* qkv_s  = w_s + 36*CH;              // 9252
    float* kv_s   = qkv_s + 36*QSTR;          // 144
    float* ksum_s = kv_s + 144;               // 12
    float* vsum_s = ksum_s + 12;              // 12

    const int tid = threadIdx.x;
    const int blk = blockIdx.x;
    const int b   = blk >> 8;
    const int wIdx = blk & 255;
    const int h0 = (wIdx >> 4) * WS;
    const int w0 = (wIdx & 15) * WS;

    // token owned by this thread (for loads / epilogue)
    const int hl = tid >> 4, wl = tid & 15;
    const int pix = (h0 + hl) * IMG + (w0 + wl);

    // stage x window: x_s[c][n]
    {
        const float* xb = x + b*CH*HW + pix;
        #pragma unroll 4
        for (int c = 0; c < CH; c++)
            x_s[c*NTOK + tid] = xb[c*HW];
    }

    // GEMM thread mapping: 64 col-groups x 4 row-groups
    const int tx = tid & 63, ty = tid >> 6;
    const int n0 = tx * 4;        // 4 consecutive tokens
    const int r0 = ty * 9;        // 9 rows of the 36-row chunk

    for (int h = 0; h < NH; h++) {
        __syncthreads();   // protects x_s (h=0), w_s & qkv_s reuse (h>0)

        // load W chunk for this head: rows 0..11 = q, 12..23 = k, 24..35 = v
        for (int i = tid; i < 36*CH; i += 256) {
            int r = i / CH, c = i - r*CH;
            int grow = (r < 12) ? (h*DH + r)
                     : (r < 24) ? (CH + h*DH + (r - 12))
                                : (2*CH + h*DH + (r - 24));
            w_s[r*CH + c] = w_qkv[grow*CH + c];
        }
        __syncthreads();

        // 36x256 = W(36x96) @ X(96x256), 9x4 micro-tile
        float acc[9][4];
        #pragma unroll
        for (int i = 0; i < 9; i++)
            #pragma unroll
            for (int j = 0; j < 4; j++) acc[i][j] = 0.f;

        #pragma unroll 2
        for (int c = 0; c < CH; c += 2) {
            float4 a0 = *reinterpret_cast<const float4*>(&x_s[c*NTOK + n0]);
            float4 a1 = *reinterpret_cast<const float4*>(&x_s[(c+1)*NTOK + n0]);
            #pragma unroll
            for (int i = 0; i < 9; i++) {
                float2 wv = *reinterpret_cast<const float2*>(&w_s[(r0+i)*CH + c]);
                acc[i][0] = fmaf(wv.x, a0.x, acc[i][0]);
                acc[i][1] = fmaf(wv.x, a0.y, acc[i][1]);
                acc[i][2] = fmaf(wv.x, a0.z, acc[i][2]);
                acc[i][3] = fmaf(wv.x, a0.w, acc[i][3]);
                acc[i][0] = fmaf(wv.y, a1.x, acc[i][0]);
                acc[i][1] = fmaf(wv.y, a1.y, acc[i][1]);
                acc[i][2] = fmaf(wv.y, a1.z, acc[i][2]);
                acc[i][3] = fmaf(wv.y, a1.w, acc[i][3]);
            }
        }
        #pragma unroll
        for (int i = 0; i < 9; i++)
            #pragma unroll
            for (int j = 0; j < 4; j++)
                qkv_s[(r0+i)*QSTR + n0 + j] = acc[i][j];
        __syncthreads();

        // per-token l2 normalization: q kept in registers, k written back
        float qn[12];
        {
            float s = 0.f;
            #pragma unroll
            for (int m = 0; m < 12; m++) { qn[m] = qkv_s[m*QSTR + tid]; s = fmaf(qn[m], qn[m], s); }
            float r = rsqrtf(s);
            #pragma unroll
            for (int m = 0; m < 12; m++) qn[m] *= r;
        }
        {
            float kr[12]; float s = 0.f;
            #pragma unroll
            for (int m = 0; m < 12; m++) { kr[m] = qkv_s[(12+m)*QSTR + tid]; s = fmaf(kr[m], kr[m], s); }
            float r = rsqrtf(s);
            #pragma unroll
            for (int m = 0; m < 12; m++) qkv_s[(12+m)*QSTR + tid] = kr[m] * r;
        }
        __syncthreads();

        // kv[m][c] = sum_n k[m][n]*v[c][n] ; ksum[m] ; vsum[c]
        if (tid < 144) {
            int m = tid / 12, c2 = tid - (tid/12)*12;
            const float* kr = &qkv_s[(12+m)*QSTR];
            const float* vr = &qkv_s[(24+c2)*QSTR];
            float s = 0.f;
            #pragma unroll 4
            for (int n = 0; n < NTOK; n++) s = fmaf(kr[n], vr[n], s);
            kv_s[m*12 + c2] = s;
        } else if (tid < 156) {
            int m = tid - 144;
            const float* kr = &qkv_s[(12+m)*QSTR];
            float s = 0.f;
            #pragma unroll 4
            for (int n = 0; n < NTOK; n++) s += kr[n];
            ksum_s[m] = s + EPS;
        } else if (tid < 168) {
            int c2 = tid - 156;
            const float* vr = &qkv_s[(24+c2)*QSTR];
            float s = 0.f;
            #pragma unroll 4
            for (int n = 0; n < NTOK; n++) s += vr[n];
            vsum_s[c2] = s;
        }
        __syncthreads();

        // epilogue: out[c][n] = (q·kv[:,c] + vsum[c]) * tailor[n]
        float denom = (float)NTOK;
        #pragma unroll
        for (int m = 0; m < 12; m++) denom = fmaf(qn[m], ksum_s[m], denom);
        float tail = 1.0f / denom;

        float* ob = g_out + (b*CH + h*DH)*HW + pix;
        #pragma unroll
        for (int c2 = 0; c2 < 12; c2++) {
            float v = vsum_s[c2];
            #pragma unroll
            for (int m = 0; m < 12; m++) v = fmaf(qn[m], kv_s[m*12 + c2], v);
            ob[c2*HW] = v * tail;
        }
    }
}

// ---------------------------------------------------------------------------
// K2: proj GEMM y = w_proj(96x96) @ out(96 x 524288) + fused BN statistics.
// Block handles 512 columns (2 per thread), 3 chunks of 32 output rows.
// ---------------------------------------------------------------------------
__global__ void __launch_bounds__(256)
k_proj(const float* __restrict__ w_proj)
{
    __shared__ float w_t[CH*CH];     // transposed: w_t[c][o]
    __shared__ float red_s[2*CH];

    const int tid = threadIdx.x;
    for (int i = tid; i < CH*CH; i += 256) {
        int o = i / CH, c = i - o*CH;
        w_t[c*CH + o] = w_proj[i];
    }
    if (tid < 2*CH) red_s[tid] = 0.f;
    __syncthreads();

    const int col0 = blockIdx.x * 512 + tid;      // second col = col0+256
    const int b = col0 >> 16;                     // / HW
    const int p = col0 & (HW - 1);
    const float* src = g_out + b*CH*HW + p;
    float*       dst = g_y   + b*CH*HW + p;

    #pragma unroll 1
    for (int chk = 0; chk < 3; chk++) {
        float acc0[32], acc1[32];
        #pragma unroll
        for (int o = 0; o < 32; o++) { acc0[o] = 0.f; acc1[o] = 0.f; }

        #pragma unroll 2
        for (int c = 0; c < CH; c++) {
            float v0 = src[c*HW];
            float v1 = src[c*HW + 256];
            const float4* wt = reinterpret_cast<const float4*>(&w_t[c*CH + chk*32]);
            #pragma unroll
            for (int o4 = 0; o4 < 8; o4++) {
                float4 w = wt[o4];
                acc0[o4*4+0] = fmaf(w.x, v0, acc0[o4*4+0]);
                acc1[o4*4+0] = fmaf(w.x, v1, acc1[o4*4+0]);
                acc0[o4*4+1] = fmaf(w.y, v0, acc0[o4*4+1]);
                acc1[o4*4+1] = fmaf(w.y, v1, acc1[o4*4+1]);
                acc0[o4*4+2] = fmaf(w.z, v0, acc0[o4*4+2]);
                acc1[o4*4+2] = fmaf(w.z, v1, acc1[o4*4+2]);
                acc0[o4*4+3] = fmaf(w.w, v0, acc0[o4*4+3]);
                acc1[o4*4+3] = fmaf(w.w, v1, acc1[o4*4+3]);
            }
        }
        #pragma unroll
        for (int o = 0; o < 32; o++) {
            int oc = chk*32 + o;
            dst[oc*HW]       = acc0[o];
            dst[oc*HW + 256] = acc1[o];
            float s = acc0[o] + acc1[o];
            float q = fmaf(acc0[o], acc0[o], acc1[o]*acc1[o]);
            #pragma unroll
            for (int d = 16; d > 0; d >>= 1) {
                s += __shfl_xor_sync(0xffffffffu, s, d);
                q += __shfl_xor_sync(0xffffffffu, q, d);
            }
            if ((tid & 31) == 0) {
                atomicAdd(&red_s[oc], s);
                atomicAdd(&red_s[CH + oc], q);
            }
        }
    }
    __syncthreads();
    if (tid < CH) {
        atomicAdd(&g_sum[tid], red_s[tid]);
        atomicAdd(&g_sq[tid],  red_s[CH + tid]);
    }
}

// ---------------------------------------------------------------------------
// K3: per-channel BN scale/shift
// ---------------------------------------------------------------------------
__global__ void k_bnprep(const float* __restrict__ gamma, const float* __restrict__ beta)
{
    int c = threadIdx.x;
    if (c < CH) {
        const float inv_n = 1.0f / (float)NPIX;
        float mean = g_sum[c] * inv_n;
        float var  = fmaf(-mean, mean, g_sq[c] * inv_n);
        float rstd = rsqrtf(var + BN_EPS);
        float sc = rstd * gamma[c];
        g_scale[c] = sc;
        g_shift[c] = fmaf(-mean, sc, beta[c]);
    }
}

// ---------------------------------------------------------------------------
// K4: apply BN (vectorized float4)
// ---------------------------------------------------------------------------
__global__ void __launch_bounds__(256)
k_bnapply(float* __restrict__ out)
{
    int i = blockIdx.x * 256 + threadIdx.x;     // float4 index, grid covers exactly
    int c = (i >> 14) % CH;                     // (i*4 / HW) % CH, HW = 2^16
    float sc = g_scale[c], sh = g_shift[c];
    float4 v = reinterpret_cast<const float4*>(g_y)[i];
    v.x = fmaf(v.x, sc, sh);
    v.y = fmaf(v.y, sc, sh);
    v.z = fmaf(v.z, sc, sh);
    v.w = fmaf(v.w, sc, sh);
    reinterpret_cast<float4*>(out)[i] = v;
}

// ---------------------------------------------------------------------------
extern "C" void kernel_launch(void* const* d_in, const int* in_sizes, int n_in,
                              void* d_out, int out_size)
{
    const float* x      = (const float*)d_in[0];
    const float* w_qkv  = (const float*)d_in[1];
    const float* w_proj = (const float*)d_in[2];
    const float* gamma  = (const float*)d_in[3];
    const float* beta   = (const float*)d_in[4];

    const int smem1 = (CH*NTOK + 36*CH + 36*QSTR + 144 + 12 + 12) * (int)sizeof(float);
    cudaFuncSetAttribute(k_qkv_attn, cudaFuncAttributeMaxDynamicSharedMemorySize, smem1);

    k_zero<<<1, 128>>>();
    k_qkv_attn<<<NWIN, 256, smem1>>>(x, w_qkv);
    k_proj<<<NPIX/512, 256>>>(w_proj);
    k_bnprep<<<1, 128>>>(gamma, beta);
    k_bnapply<<<TOTAL/4/256, 256>>>((float*)d_out);
}